// round 10
// baseline (speedup 1.0000x reference)
#include <cuda_runtime.h>
#include <cuda_fp16.h>
#include <cstdint>

// Problem constants (GCNLayer_12317966205308)
#define NN 50000
#define EE 800000
#define D  64

__device__ __align__(256) float  g_acc[NN * D];   // accumulator (init = self-loop term, f32)
__device__ __align__(256) __half g_xwsh[NN * D];  // fp16 copy of dis[j]*(x[j]@W) for gather
__device__ __align__(256) float  g_dis[NN];       // rsqrt(deg)
__device__ __align__(256) int    g_deg[NN];       // zero-init at load; k_xw resets to 0

// ---------------------------------------------------------------------------
// K1: edge-count histogram over dst (g_deg starts at 0: zero-init / reset by k_xw)
__global__ void k_deg_count(const int* __restrict__ ei, int E) {
    int q = blockIdx.x * blockDim.x + threadIdx.x;
    int e0 = q * 4;
    if (e0 + 4 <= E) {
        int4 d = *reinterpret_cast<const int4*>(ei + E + e0);   // E % 4 == 0
        atomicAdd(&g_deg[d.x], 1);
        atomicAdd(&g_deg[d.y], 1);
        atomicAdd(&g_deg[d.z], 1);
        atomicAdd(&g_deg[d.w], 1);
    } else {
        for (int e = e0; e < E; e++) atomicAdd(&g_deg[ei[E + e]], 1);
    }
}

__device__ __forceinline__ unsigned long long pack2(float lo, float hi) {
    unsigned long long r;
    asm("mov.b64 %0, {%1, %2};" : "=l"(r) : "f"(lo), "f"(hi));
    return r;
}
__device__ __forceinline__ void unpack2(unsigned long long p, float& lo, float& hi) {
    asm("mov.b64 {%0, %1}, %2;" : "=f"(lo), "=f"(hi) : "l"(p));
}
__device__ __forceinline__ unsigned long long fma2(unsigned long long a,
                                                   unsigned long long b,
                                                   unsigned long long c) {
    unsigned long long d;
    asm("fma.rn.f32x2 %0, %1, %2, %3;" : "=l"(d) : "l"(a), "l"(b), "l"(c));
    return d;
}

// K2: v = dis * (x @ W); acc = v (f32 self-loop term); xwsh = half(v); store dis.
// deg = g_deg + 1 (self loop); resets g_deg to 0 for the next replay.
// 256 threads/block, 64 rows/block, 4x4 tile per thread, packed f32x2 FMAs.
__global__ void __launch_bounds__(256) k_xw(const float* __restrict__ x,
                                            const float* __restrict__ W, int n) {
    __shared__ float Ws[D * D];        // [k][c]
    __shared__ float xs[64][D + 1];    // [r][k], padded
    int tid = threadIdx.x;
    int row0 = blockIdx.x * 64;

    {
        const float4* W4 = (const float4*)W;
        float4* Ws4 = (float4*)Ws;
        #pragma unroll
        for (int i = 0; i < 4; i++) Ws4[tid + 256 * i] = W4[tid + 256 * i];
    }
    #pragma unroll
    for (int i = 0; i < 4; i++) {
        int f = tid + 256 * i;
        int r = f >> 4, c4 = f & 15;
        int node = row0 + r;
        float4 v = (node < n) ? ((const float4*)(x + (size_t)node * D))[c4]
                              : make_float4(0.f, 0.f, 0.f, 0.f);
        xs[r][c4 * 4 + 0] = v.x; xs[r][c4 * 4 + 1] = v.y;
        xs[r][c4 * 4 + 2] = v.z; xs[r][c4 * 4 + 3] = v.w;
    }
    __syncthreads();

    int cg = tid & 15;   // cols [cg*4, cg*4+4)
    int rg = tid >> 4;   // rows [rg*4, rg*4+4)
    unsigned long long a01[4] = {0, 0, 0, 0};   // (c0,c1) packed per row
    unsigned long long a23[4] = {0, 0, 0, 0};   // (c2,c3) packed per row
    #pragma unroll 8
    for (int k = 0; k < D; k++) {
        float4 w = *(const float4*)&Ws[k * D + cg * 4];
        unsigned long long wxy = pack2(w.x, w.y);
        unsigned long long wzw = pack2(w.z, w.w);
        #pragma unroll
        for (int rr = 0; rr < 4; rr++) {
            float xv = xs[rg * 4 + rr][k];
            unsigned long long xp = pack2(xv, xv);
            a01[rr] = fma2(xp, wxy, a01[rr]);
            a23[rr] = fma2(xp, wzw, a23[rr]);
        }
    }

    #pragma unroll
    for (int rr = 0; rr < 4; rr++) {
        int node = row0 + rg * 4 + rr;
        if (node < n) {
            int degm1 = g_deg[node];                  // broadcast load, same half-warp
            float dis = rsqrtf((float)(degm1 + 1));   // +1 = self loop
            float4 v;
            unpack2(a01[rr], v.x, v.y);
            unpack2(a23[rr], v.z, v.w);
            v.x *= dis; v.y *= dis; v.z *= dis; v.w *= dis;
            ((float4*)(g_acc + (size_t)node * D))[cg] = v;   // self-loop term
            __half2 h0 = __floats2half2_rn(v.x, v.y);
            __half2 h1 = __floats2half2_rn(v.z, v.w);
            ((__half2*)(g_xwsh + (size_t)node * D))[cg * 2 + 0] = h0;
            ((__half2*)(g_xwsh + (size_t)node * D))[cg * 2 + 1] = h1;
            if (cg == 0) {
                g_dis[node] = dis;
                g_deg[node] = 0;    // reset for next replay (after the read above)
            }
        }
    }
}

__device__ __forceinline__ void red4(float* ap, float4 v) {
    asm volatile("red.global.add.v4.f32 [%0], {%1, %2, %3, %4};"
                 :: "l"(ap), "f"(v.x), "f"(v.y), "f"(v.z), "f"(v.w)
                 : "memory");
}

__device__ __forceinline__ float4 gather_h4(const __half* base, int lane) {
    uint2 raw = *reinterpret_cast<const uint2*>(base + lane * 4);
    __half2 h0 = *reinterpret_cast<__half2*>(&raw.x);
    __half2 h1 = *reinterpret_cast<__half2*>(&raw.y);
    float2 f0 = __half22float2(h0);
    float2 f1 = __half22float2(h1);
    return make_float4(f0.x, f0.y, f1.x, f1.y);
}

// K3: edge scatter. 16 threads x 8 edges per thread-group: two int4 index
// loads, 8 independent fp16 gathers (MLP=8), 8 f32 vector REDs.
__global__ void k_scatter(const int* __restrict__ ei, int E) {
    int t = blockIdx.x * blockDim.x + threadIdx.x;
    int lane = t & 15;
    int o = t >> 4;
    int e0 = o * 8;
    if (e0 >= E) return;

    if (e0 + 8 <= E) {   // fast path; E % 4 == 0 and usually % 8
        int4 sa = *reinterpret_cast<const int4*>(ei + e0);
        int4 sb = *reinterpret_cast<const int4*>(ei + e0 + 4);
        int4 da = *reinterpret_cast<const int4*>(ei + E + e0);
        int4 db = *reinterpret_cast<const int4*>(ei + E + e0 + 4);
        float4 v0 = gather_h4(g_xwsh + (size_t)sa.x * D, lane);
        float4 v1 = gather_h4(g_xwsh + (size_t)sa.y * D, lane);
        float4 v2 = gather_h4(g_xwsh + (size_t)sa.z * D, lane);
        float4 v3 = gather_h4(g_xwsh + (size_t)sa.w * D, lane);
        float4 v4 = gather_h4(g_xwsh + (size_t)sb.x * D, lane);
        float4 v5 = gather_h4(g_xwsh + (size_t)sb.y * D, lane);
        float4 v6 = gather_h4(g_xwsh + (size_t)sb.z * D, lane);
        float4 v7 = gather_h4(g_xwsh + (size_t)sb.w * D, lane);
        red4(g_acc + (size_t)da.x * D + lane * 4, v0);
        red4(g_acc + (size_t)da.y * D + lane * 4, v1);
        red4(g_acc + (size_t)da.z * D + lane * 4, v2);
        red4(g_acc + (size_t)da.w * D + lane * 4, v3);
        red4(g_acc + (size_t)db.x * D + lane * 4, v4);
        red4(g_acc + (size_t)db.y * D + lane * 4, v5);
        red4(g_acc + (size_t)db.z * D + lane * 4, v6);
        red4(g_acc + (size_t)db.w * D + lane * 4, v7);
    } else {
        for (int e = e0; e < E; e++) {
            int src = ei[e], dst = ei[E + e];
            float4 v = gather_h4(g_xwsh + (size_t)src * D, lane);
            red4(g_acc + (size_t)dst * D + lane * 4, v);
        }
    }
}

// K4: out = relu(dis * acc + b). 2 independent node-chunks per thread (MLP),
// streaming stores (out is write-once; keep L2 for acc/xws).
__global__ void k_final(const float* __restrict__ b, float* __restrict__ out, int n) {
    int H = n * 8;                       // half of the n*16 float4 slots
    int t = blockIdx.x * blockDim.x + threadIdx.x;
    if (t >= H) return;
    int s0 = t, s1 = t + H;

    float4 a0 = reinterpret_cast<const float4*>(g_acc)[s0];
    float4 a1 = reinterpret_cast<const float4*>(g_acc)[s1];
    float dis0 = g_dis[s0 >> 4];
    float dis1 = g_dis[s1 >> 4];
    float4 b0 = reinterpret_cast<const float4*>(b)[s0 & 15];
    float4 b1 = reinterpret_cast<const float4*>(b)[s1 & 15];

    float4 o0, o1;
    o0.x = fmaxf(fmaf(dis0, a0.x, b0.x), 0.0f);
    o0.y = fmaxf(fmaf(dis0, a0.y, b0.y), 0.0f);
    o0.z = fmaxf(fmaf(dis0, a0.z, b0.z), 0.0f);
    o0.w = fmaxf(fmaf(dis0, a0.w, b0.w), 0.0f);
    o1.x = fmaxf(fmaf(dis1, a1.x, b1.x), 0.0f);
    o1.y = fmaxf(fmaf(dis1, a1.y, b1.y), 0.0f);
    o1.z = fmaxf(fmaf(dis1, a1.z, b1.z), 0.0f);
    o1.w = fmaxf(fmaf(dis1, a1.w, b1.w), 0.0f);
    __stcs(reinterpret_cast<float4*>(out) + s0, o0);
    __stcs(reinterpret_cast<float4*>(out) + s1, o1);
}

// ---------------------------------------------------------------------------
extern "C" void kernel_launch(void* const* d_in, const int* in_sizes, int n_in,
                              void* d_out, int out_size) {
    const float* x  = (const float*)d_in[0];   // [N, 64] f32
    const int*   ei = (const int*)d_in[1];     // [2, E] int32
    const float* W  = (const float*)d_in[2];   // [64, 64] f32
    const float* b  = (const float*)d_in[3];   // [64] f32
    float* out = (float*)d_out;

    int N = in_sizes[0] / D;
    int E = in_sizes[1] / 2;
    int quads = (E + 3) / 4;
    int octs  = (E + 7) / 8;

    k_deg_count<<<(quads + 255) / 256, 256>>>(ei, E);
    k_xw<<<(N + 63) / 64, 256>>>(x, W, N);
    {
        long long work = (long long)octs * 16;
        k_scatter<<<(int)((work + 255) / 256), 256>>>(ei, E);
    }
    {
        int work = N * 8;
        k_final<<<(work + 255) / 256, 256>>>(b, out, N);
    }
}